// round 2
// baseline (speedup 1.0000x reference)
#include <cuda_runtime.h>
#include <cuda_bf16.h>

#define N_ROWS 65536
#define DIMS   64
#define KCODES 512
#define Q_OFF  1
#define Q_SIZE (N_ROWS * DIMS)          // 4194304
#define PERP_OFF (Q_OFF + Q_SIZE)       // 4194305
#define ENC_OFF  (PERP_OFF + 1)         // 4194306  (byte offset % 16 == 8 -> float2 OK)
#define FLT_EPS_32 1.1920929e-07f

// ---- scratch (no allocation allowed) ----
__device__ int    g_idx[N_ROWS];
__device__ int    g_counts[KCODES];
__device__ double g_errsum;
__device__ float  g_wsq[KCODES];

// packed fp32x2 FMA (sm_103a): acc += a*b elementwise on 2 floats
#define FMA2(acc, a, b) asm("fma.rn.f32x2 %0, %1, %2, %0;" : "+l"(acc) : "l"(a), "l"(b))

__device__ __forceinline__ float f2lo(unsigned long long u) { return __uint_as_float((unsigned)u); }
__device__ __forceinline__ float f2hi(unsigned long long u) { return __uint_as_float((unsigned)(u >> 32)); }

// ---------------- prep: zero accumulators, compute ||w_k||^2 ----------------
__global__ void vq_prep(const float* __restrict__ w) {
    int k = threadIdx.x;            // 512 threads
    if (k == 0) g_errsum = 0.0;
    g_counts[k] = 0;
    const float* wr = w + k * DIMS;
    float s = 0.0f;
    for (int d = 0; d < DIMS; d++) {
        float v = wr[d];
        s = __fadd_rn(s, __fmul_rn(v, v));   // square rounded, then summed (mimic jnp)
    }
    g_wsq[k] = s;
}

// ---------------- main: argmin + quantized_st + loss partials + histogram ----------------
__global__ void __launch_bounds__(256) vq_main(const float* __restrict__ x,
                                               const float* __restrict__ w,
                                               float* __restrict__ qout) {
    extern __shared__ float sm[];
    float* sw   = sm;                      // 32768 floats (codebook)
    float* swsq = sm + KCODES * DIMS;      // 512
    int*   shist = (int*)(sm + KCODES * DIMS + KCODES); // 512

    int tid = threadIdx.x;
    for (int i = tid; i < KCODES * DIMS; i += 256) sw[i] = w[i];
    for (int i = tid; i < KCODES; i += 256) { swsq[i] = g_wsq[i]; shist[i] = 0; }
    __syncthreads();

    float errloc = 0.0f;
    int r = blockIdx.x * 256 + tid;        // grid 256 x 256 covers N exactly
    {
        const ulonglong2* xrow = (const ulonglong2*)(x + (size_t)r * DIMS);
        unsigned long long xr[32];
#pragma unroll
        for (int i = 0; i < 16; i++) { ulonglong2 t = xrow[i]; xr[2*i] = t.x; xr[2*i+1] = t.y; }

        // xsq sequentially, squares rounded individually (no FMA contraction)
        float xsq = 0.0f;
#pragma unroll
        for (int i = 0; i < 32; i++) {
            float lo = f2lo(xr[i]), hi = f2hi(xr[i]);
            xsq = __fadd_rn(xsq, __fmul_rn(lo, lo));
            xsq = __fadd_rn(xsq, __fmul_rn(hi, hi));
        }

        float bd = 3.4028235e38f;
        int   bi = 0;
        for (int k = 0; k < KCODES; k++) {
            const ulonglong2* wr = (const ulonglong2*)(sw + (k << 6));
            unsigned long long a0 = 0ull, a1 = 0ull, a2 = 0ull, a3 = 0ull;
#pragma unroll
            for (int i = 0; i < 16; i += 2) {
                ulonglong2 t0 = wr[i];
                ulonglong2 t1 = wr[i + 1];
                FMA2(a0, xr[2*i],     t0.x);
                FMA2(a1, xr[2*i + 1], t0.y);
                FMA2(a2, xr[2*i + 2], t1.x);
                FMA2(a3, xr[2*i + 3], t1.y);
            }
            float s = ((f2lo(a0) + f2hi(a0)) + (f2lo(a1) + f2hi(a1)))
                    + ((f2lo(a2) + f2hi(a2)) + (f2lo(a3) + f2hi(a3)));
            // dist = fl( fl(xsq + wsq[k]) - 2*s )  — same association as reference
            float dist = __fadd_rn(__fadd_rn(xsq, swsq[k]), -(2.0f * s));
            if (dist < bd) { bd = dist; bi = k; }
        }

        g_idx[r] = bi;
        atomicAdd(&shist[bi], 1);

        // quantized_st = fl(x + fl(q - x)); loss term uses (q - x)^2
        // qout row starts at float offset 1 + 64r (== 1 mod 4): element j is
        // 16B-aligned iff j % 4 == 3. Scalars at j in {0,1,2,63}, float4 at j=3..62.
        float*       qo = qout + (size_t)r * DIMS;
        const float* qr = sw + (bi << 6);

#pragma unroll
        for (int jj = 0; jj < 3; jj++) {
            float xv = (jj & 1) ? f2hi(xr[jj >> 1]) : f2lo(xr[jj >> 1]);
            float d  = __fsub_rn(qr[jj], xv);
            qo[jj] = __fadd_rn(xv, d);
            errloc += __fmul_rn(d, d);
        }
        {
            float xv = f2hi(xr[31]);
            float d  = __fsub_rn(qr[63], xv);
            qo[63] = __fadd_rn(xv, d);
            errloc += __fmul_rn(d, d);
        }
#pragma unroll
        for (int i = 0; i < 15; i++) {
            int j = 3 + 4 * i;   // j, j+1, j+2, j+3  (j odd)
            float x0 = f2hi(xr[(j    ) >> 1]);
            float x1 = f2lo(xr[(j + 1) >> 1]);
            float x2 = f2hi(xr[(j + 2) >> 1]);
            float x3 = f2lo(xr[(j + 3) >> 1]);
            float d0 = __fsub_rn(qr[j    ], x0);
            float d1 = __fsub_rn(qr[j + 1], x1);
            float d2 = __fsub_rn(qr[j + 2], x2);
            float d3 = __fsub_rn(qr[j + 3], x3);
            float4 o;
            o.x = __fadd_rn(x0, d0); o.y = __fadd_rn(x1, d1);
            o.z = __fadd_rn(x2, d2); o.w = __fadd_rn(x3, d3);
            *reinterpret_cast<float4*>(qo + j) = o;
            errloc += __fmul_rn(d0,d0) + __fmul_rn(d1,d1) + __fmul_rn(d2,d2) + __fmul_rn(d3,d3);
        }
    }
    __syncthreads();
    for (int i = tid; i < KCODES; i += 256)
        if (shist[i]) atomicAdd(&g_counts[i], shist[i]);
#pragma unroll
    for (int o = 16; o > 0; o >>= 1) errloc += __shfl_down_sync(0xffffffffu, errloc, o);
    if ((tid & 31) == 0) atomicAdd(&g_errsum, (double)errloc);
}

// ---------------- encodings: one-hot write, float2 per thread (8B-aligned base) ----------------
__global__ void __launch_bounds__(256) vq_enc(float* __restrict__ enc) {
    unsigned i = blockIdx.x * blockDim.x + threadIdx.x;   // 16,777,216 float2s
    unsigned n = i >> 8;                                  // row (256 float2s per row of 512)
    int j = (int)((i & 255u) << 1);
    int b = g_idx[n];
    float2 v;
    v.x = (j     == b) ? 1.0f : 0.0f;
    v.y = (j + 1 == b) ? 1.0f : 0.0f;
    reinterpret_cast<float2*>(enc)[i] = v;
}

// ---------------- finalize: loss + perplexity ----------------
__global__ void vq_fin(float* __restrict__ out_loss, float* __restrict__ out_perp) {
    __shared__ float red[KCODES];
    int t = threadIdx.x;
    float p = (float)g_counts[t] / 65536.0f;
    red[t] = __fmul_rn(p, logf(__fadd_rn(p, FLT_EPS_32)));
    __syncthreads();
    for (int s = 256; s > 0; s >>= 1) {
        if (t < s) red[t] += red[t + s];
        __syncthreads();
    }
    if (t == 0) {
        *out_perp = expf(-red[0]);
        float m = (float)(g_errsum / 4194304.0);
        *out_loss = __fadd_rn(m, __fmul_rn(0.25f, m));   // q_latent + 0.25*e_latent, equal values
    }
}

extern "C" void kernel_launch(void* const* d_in, const int* in_sizes, int n_in,
                              void* d_out, int out_size) {
    const float* x = (const float*)d_in[0];
    const float* w = (const float*)d_in[1];
    if (n_in >= 2 && in_sizes[0] == KCODES * DIMS) {  // robustness to input ordering
        const float* t = x; x = w; w = t;
    }
    float* out  = (float*)d_out;
    float* qout = out + Q_OFF;
    float* perp = out + PERP_OFF;
    float* enc  = out + ENC_OFF;

    static const int SMEM_MAIN = (KCODES * DIMS + KCODES) * 4 + KCODES * 4; // 135168
    cudaFuncSetAttribute(vq_main, cudaFuncAttributeMaxDynamicSharedMemorySize, SMEM_MAIN);

    vq_prep<<<1, KCODES>>>(w);
    vq_main<<<256, 256, SMEM_MAIN>>>(x, w, qout);
    vq_enc<<<(N_ROWS * KCODES / 2) / 256, 256>>>(enc);
    vq_fin<<<1, KCODES>>>(out, perp);
}

// round 3
// speedup vs baseline: 1.2701x; 1.2701x over previous
#include <cuda_runtime.h>
#include <cuda_bf16.h>

#define N_ROWS 65536
#define DIMS   64
#define KCODES 512
#define Q_OFF  1
#define Q_SIZE (N_ROWS * DIMS)          // 4194304
#define PERP_OFF (Q_OFF + Q_SIZE)       // 4194305
#define ENC_OFF  (PERP_OFF + 1)         // 4194306  (byte offset % 16 == 8 -> float2 OK)
#define FLT_EPS_32 1.1920929e-07f
#define TPB 448                          // 14 warps, 1 block/SM, 148 blocks = 1 wave

// ---- scratch (no allocation allowed) ----
__device__ int    g_idx[N_ROWS];
__device__ int    g_counts[KCODES];
__device__ double g_errsum;
__device__ float  g_wsq[KCODES];

// packed fp32x2 FMA (sm_103a): acc += a*b elementwise on 2 floats
#define FMA2(acc, a, b) asm("fma.rn.f32x2 %0, %1, %2, %0;" : "+l"(acc) : "l"(a), "l"(b))

__device__ __forceinline__ float f2lo(unsigned long long u) { return __uint_as_float((unsigned)u); }
__device__ __forceinline__ float f2hi(unsigned long long u) { return __uint_as_float((unsigned)(u >> 32)); }

// ---------------- prep: zero accumulators, compute ||w_k||^2 ----------------
__global__ void vq_prep(const float* __restrict__ w) {
    int k = threadIdx.x;            // 512 threads
    if (k == 0) g_errsum = 0.0;
    g_counts[k] = 0;
    const float* wr = w + k * DIMS;
    float s = 0.0f;
    for (int d = 0; d < DIMS; d++) {
        float v = wr[d];
        s = __fadd_rn(s, __fmul_rn(v, v));   // square rounded, then summed (mimic jnp)
    }
    g_wsq[k] = s;
}

// ---------------- main: argmin + quantized_st + loss partials + histogram ----------------
__global__ void __launch_bounds__(TPB, 1) vq_main(const float* __restrict__ x,
                                                  const float* __restrict__ w,
                                                  float* __restrict__ qout) {
    extern __shared__ float sm[];
    float* sw   = sm;                      // 32768 floats (codebook)
    float* swsq = sm + KCODES * DIMS;      // 512
    int*   shist = (int*)(sm + KCODES * DIMS + KCODES); // 512

    int tid = threadIdx.x;
    for (int i = tid; i < KCODES * DIMS / 4; i += TPB)
        ((float4*)sw)[i] = ((const float4*)w)[i];
    for (int i = tid; i < KCODES; i += TPB) { swsq[i] = g_wsq[i]; shist[i] = 0; }
    __syncthreads();

    float errloc = 0.0f;
    int r = blockIdx.x * TPB + tid;
    if (r < N_ROWS) {
        const ulonglong2* xrow = (const ulonglong2*)(x + (size_t)r * DIMS);
        unsigned long long xr[32];
#pragma unroll
        for (int i = 0; i < 16; i++) { ulonglong2 t = xrow[i]; xr[2*i] = t.x; xr[2*i+1] = t.y; }

        // xsq sequentially, squares rounded individually (bit-identical to R2)
        float xsq = 0.0f;
#pragma unroll
        for (int i = 0; i < 32; i++) {
            float lo = f2lo(xr[i]), hi = f2hi(xr[i]);
            xsq = __fadd_rn(xsq, __fmul_rn(lo, lo));
            xsq = __fadd_rn(xsq, __fmul_rn(hi, hi));
        }

        float bd = 3.4028235e38f;
        int   bi = 0;
#pragma unroll 2
        for (int k = 0; k < KCODES; k++) {
            const ulonglong2* wr = (const ulonglong2*)(sw + (k << 6));
            unsigned long long a0 = 0ull, a1 = 0ull, a2 = 0ull, a3 = 0ull;
#pragma unroll
            for (int i = 0; i < 16; i += 2) {
                ulonglong2 t0 = wr[i];
                ulonglong2 t1 = wr[i + 1];
                FMA2(a0, xr[2*i],     t0.x);
                FMA2(a1, xr[2*i + 1], t0.y);
                FMA2(a2, xr[2*i + 2], t1.x);
                FMA2(a3, xr[2*i + 3], t1.y);
            }
            float s = ((f2lo(a0) + f2hi(a0)) + (f2lo(a1) + f2hi(a1)))
                    + ((f2lo(a2) + f2hi(a2)) + (f2lo(a3) + f2hi(a3)));
            // dist = fl( fl(xsq + wsq[k]) - 2*s )  — bit-identical to R2
            float dist = __fadd_rn(__fadd_rn(xsq, swsq[k]), -(2.0f * s));
            if (dist < bd) { bd = dist; bi = k; }
        }

        g_idx[r] = bi;
        atomicAdd(&shist[bi], 1);

        // quantized_st = fl(x + fl(q - x)); loss term uses (q - x)^2
        // qout row starts at float offset 1 + 64r: element j 16B-aligned iff j%4==3.
        float*       qo = qout + (size_t)r * DIMS;
        const float* qr = sw + (bi << 6);

#pragma unroll
        for (int jj = 0; jj < 3; jj++) {
            float xv = (jj & 1) ? f2hi(xr[jj >> 1]) : f2lo(xr[jj >> 1]);
            float d  = __fsub_rn(qr[jj], xv);
            qo[jj] = __fadd_rn(xv, d);
            errloc += __fmul_rn(d, d);
        }
        {
            float xv = f2hi(xr[31]);
            float d  = __fsub_rn(qr[63], xv);
            qo[63] = __fadd_rn(xv, d);
            errloc += __fmul_rn(d, d);
        }
#pragma unroll
        for (int i = 0; i < 15; i++) {
            int j = 3 + 4 * i;
            float x0 = f2hi(xr[(j    ) >> 1]);
            float x1 = f2lo(xr[(j + 1) >> 1]);
            float x2 = f2hi(xr[(j + 2) >> 1]);
            float x3 = f2lo(xr[(j + 3) >> 1]);
            float d0 = __fsub_rn(qr[j    ], x0);
            float d1 = __fsub_rn(qr[j + 1], x1);
            float d2 = __fsub_rn(qr[j + 2], x2);
            float d3 = __fsub_rn(qr[j + 3], x3);
            float4 o;
            o.x = __fadd_rn(x0, d0); o.y = __fadd_rn(x1, d1);
            o.z = __fadd_rn(x2, d2); o.w = __fadd_rn(x3, d3);
            *reinterpret_cast<float4*>(qo + j) = o;
            errloc += __fmul_rn(d0,d0) + __fmul_rn(d1,d1) + __fmul_rn(d2,d2) + __fmul_rn(d3,d3);
        }
    }
    __syncthreads();
    for (int i = tid; i < KCODES; i += TPB)
        if (shist[i]) atomicAdd(&g_counts[i], shist[i]);
#pragma unroll
    for (int o = 16; o > 0; o >>= 1) errloc += __shfl_down_sync(0xffffffffu, errloc, o);
    if ((tid & 31) == 0) atomicAdd(&g_errsum, (double)errloc);
}

// ---------------- encodings: zero-fill (runs on side stream, overlaps vq_main) ----------------
__global__ void __launch_bounds__(256) vq_zero(float2* __restrict__ enc2) {
    unsigned i = blockIdx.x * 256u + threadIdx.x;   // 16,777,216 float2s
    enc2[i] = make_float2(0.0f, 0.0f);
}

// ---------------- encodings: scatter the ones ----------------
__global__ void __launch_bounds__(256) vq_scatter(float* __restrict__ enc) {
    unsigned n = blockIdx.x * 256u + threadIdx.x;   // 65536 rows
    enc[(size_t)n * KCODES + g_idx[n]] = 1.0f;
}

// ---------------- finalize: loss + perplexity ----------------
__global__ void vq_fin(float* __restrict__ out_loss, float* __restrict__ out_perp) {
    __shared__ float red[16];
    int t = threadIdx.x;                  // 512 threads
    float p = (float)g_counts[t] * (1.0f / 65536.0f);
    float v = p * __logf(p + FLT_EPS_32);
#pragma unroll
    for (int o = 16; o > 0; o >>= 1) v += __shfl_down_sync(0xffffffffu, v, o);
    if ((t & 31) == 0) red[t >> 5] = v;
    __syncthreads();
    if (t < 16) {
        float s = red[t];
#pragma unroll
        for (int o = 8; o > 0; o >>= 1) s += __shfl_down_sync(0xffffu, s, o);
        if (t == 0) {
            *out_perp = __expf(-s);
            float m = (float)(g_errsum / 4194304.0);
            *out_loss = __fadd_rn(m, __fmul_rn(0.25f, m));
        }
    }
}

extern "C" void kernel_launch(void* const* d_in, const int* in_sizes, int n_in,
                              void* d_out, int out_size) {
    const float* x = (const float*)d_in[0];
    const float* w = (const float*)d_in[1];
    if (n_in >= 2 && in_sizes[0] == KCODES * DIMS) {
        const float* t = x; x = w; w = t;
    }
    float* out  = (float*)d_out;
    float* qout = out + Q_OFF;
    float* perp = out + PERP_OFF;
    float* enc  = out + ENC_OFF;

    static cudaStream_t s2 = nullptr;
    static cudaEvent_t evF = nullptr, evJ = nullptr;
    static bool inited = false;
    if (!inited) {   // first call = eager correctness run (not under capture)
        cudaStreamCreateWithFlags(&s2, cudaStreamNonBlocking);
        cudaEventCreateWithFlags(&evF, cudaEventDisableTiming);
        cudaEventCreateWithFlags(&evJ, cudaEventDisableTiming);
        const int SMEM_MAIN = (KCODES * DIMS + KCODES) * 4 + KCODES * 4; // 135168
        cudaFuncSetAttribute(vq_main, cudaFuncAttributeMaxDynamicSharedMemorySize, SMEM_MAIN);
        inited = true;
    }
    const int SMEM_MAIN = (KCODES * DIMS + KCODES) * 4 + KCODES * 4;

    // fork: zero-fill encodings on side stream, overlapping vq_main
    cudaEventRecord(evF, 0);
    cudaStreamWaitEvent(s2, evF, 0);
    vq_zero<<<(N_ROWS * KCODES / 2) / 256, 256, 0, s2>>>((float2*)enc);
    cudaEventRecord(evJ, s2);

    vq_prep<<<1, KCODES>>>(w);
    vq_main<<<148, TPB, SMEM_MAIN>>>(x, w, qout);

    // join: scatter needs both the zero-fill and g_idx
    cudaStreamWaitEvent(0, evJ, 0);
    vq_scatter<<<N_ROWS / 256, 256>>>(enc);
    vq_fin<<<1, KCODES>>>(out, perp);
}

// round 4
// speedup vs baseline: 1.4463x; 1.1387x over previous
#include <cuda_runtime.h>
#include <cuda_bf16.h>

#define N_ROWS 65536
#define DIMS   64
#define KCODES 512
#define Q_OFF  1
#define Q_SIZE (N_ROWS * DIMS)          // 4194304
#define PERP_OFF (Q_OFF + Q_SIZE)       // 4194305
#define ENC_OFF  (PERP_OFF + 1)         // 4194306  (byte offset % 16 == 8)
#define FLT_EPS_32 1.1920929e-07f
#define TPB 448                          // 14 warps, 1 block/SM, 148 blocks = 1 wave

// ---- scratch (no allocation allowed) ----
__device__ int    g_idx[N_ROWS];
__device__ int    g_counts[KCODES];
__device__ double g_errsum;

// packed fp32x2 FMA (sm_103a): acc += a*b elementwise on 2 floats
#define FMA2(acc, a, b) asm("fma.rn.f32x2 %0, %1, %2, %0;" : "+l"(acc) : "l"(a), "l"(b))

__device__ __forceinline__ float f2lo(unsigned long long u) { return __uint_as_float((unsigned)u); }
__device__ __forceinline__ float f2hi(unsigned long long u) { return __uint_as_float((unsigned)(u >> 32)); }

// ---------------- prep: zero accumulators only ----------------
__global__ void vq_prep() {
    int k = threadIdx.x;            // 512 threads
    if (k == 0) g_errsum = 0.0;
    g_counts[k] = 0;
}

// ---------------- main: wsq + argmin + quantized_st + loss partials + histogram ----------------
__global__ void __launch_bounds__(TPB, 1) vq_main(const float* __restrict__ x,
                                                  const float* __restrict__ w,
                                                  float* __restrict__ qout) {
    extern __shared__ float sm[];
    float* sw   = sm;                      // 32768 floats (codebook)
    float* swsq = sm + KCODES * DIMS;      // 512
    int*   shist = (int*)(sm + KCODES * DIMS + KCODES); // 512

    int tid = threadIdx.x;
    for (int i = tid; i < KCODES * DIMS / 4; i += TPB)
        ((float4*)sw)[i] = ((const float4*)w)[i];
    for (int i = tid; i < KCODES; i += TPB) shist[i] = 0;
    __syncthreads();
    // ||w_k||^2 from smem copy — identical rounding to reference (square, then sum)
    for (int k = tid; k < KCODES; k += TPB) {
        const float* wr = sw + (k << 6);
        float s = 0.0f;
        for (int d = 0; d < DIMS; d++)
            s = __fadd_rn(s, __fmul_rn(wr[d], wr[d]));
        swsq[k] = s;
    }
    __syncthreads();

    float errloc = 0.0f;
    int r = blockIdx.x * TPB + tid;
    if (r < N_ROWS) {
        const ulonglong2* xrow = (const ulonglong2*)(x + (size_t)r * DIMS);
        unsigned long long xr[32];
#pragma unroll
        for (int i = 0; i < 16; i++) { ulonglong2 t = xrow[i]; xr[2*i] = t.x; xr[2*i+1] = t.y; }

        // xsq sequentially, squares rounded individually (bit-identical to R2/R3)
        float xsq = 0.0f;
#pragma unroll
        for (int i = 0; i < 32; i++) {
            float lo = f2lo(xr[i]), hi = f2hi(xr[i]);
            xsq = __fadd_rn(xsq, __fmul_rn(lo, lo));
            xsq = __fadd_rn(xsq, __fmul_rn(hi, hi));
        }

        float bd = 3.4028235e38f;
        int   bi = 0;
        for (int k = 0; k < KCODES; k++) {   // no outer unroll: keep live state small
            const ulonglong2* wr = (const ulonglong2*)(sw + (k << 6));
            unsigned long long a0 = 0ull, a1 = 0ull, a2 = 0ull, a3 = 0ull;
#pragma unroll
            for (int i = 0; i < 16; i += 2) {
                ulonglong2 t0 = wr[i];
                ulonglong2 t1 = wr[i + 1];
                FMA2(a0, xr[2*i],     t0.x);
                FMA2(a1, xr[2*i + 1], t0.y);
                FMA2(a2, xr[2*i + 2], t1.x);
                FMA2(a3, xr[2*i + 3], t1.y);
            }
            float s = ((f2lo(a0) + f2hi(a0)) + (f2lo(a1) + f2hi(a1)))
                    + ((f2lo(a2) + f2hi(a2)) + (f2lo(a3) + f2hi(a3)));
            // dist = fl( fl(xsq + wsq[k]) - 2*s )  — bit-identical to R2/R3
            float dist = __fadd_rn(__fadd_rn(xsq, swsq[k]), -(2.0f * s));
            if (dist < bd) { bd = dist; bi = k; }
        }

        g_idx[r] = bi;
        atomicAdd(&shist[bi], 1);

        // quantized_st = fl(x + fl(q - x)); loss term uses (q - x)^2
        // qout row starts at float offset 1 + 64r: element j 16B-aligned iff j%4==3.
        float*       qo = qout + (size_t)r * DIMS;
        const float* qr = sw + (bi << 6);

#pragma unroll
        for (int jj = 0; jj < 3; jj++) {
            float xv = (jj & 1) ? f2hi(xr[jj >> 1]) : f2lo(xr[jj >> 1]);
            float d  = __fsub_rn(qr[jj], xv);
            qo[jj] = __fadd_rn(xv, d);
            errloc += __fmul_rn(d, d);
        }
        {
            float xv = f2hi(xr[31]);
            float d  = __fsub_rn(qr[63], xv);
            qo[63] = __fadd_rn(xv, d);
            errloc += __fmul_rn(d, d);
        }
#pragma unroll
        for (int i = 0; i < 15; i++) {
            int j = 3 + 4 * i;
            float x0 = f2hi(xr[(j    ) >> 1]);
            float x1 = f2lo(xr[(j + 1) >> 1]);
            float x2 = f2hi(xr[(j + 2) >> 1]);
            float x3 = f2lo(xr[(j + 3) >> 1]);
            float d0 = __fsub_rn(qr[j    ], x0);
            float d1 = __fsub_rn(qr[j + 1], x1);
            float d2 = __fsub_rn(qr[j + 2], x2);
            float d3 = __fsub_rn(qr[j + 3], x3);
            float4 o;
            o.x = __fadd_rn(x0, d0); o.y = __fadd_rn(x1, d1);
            o.z = __fadd_rn(x2, d2); o.w = __fadd_rn(x3, d3);
            *reinterpret_cast<float4*>(qo + j) = o;
            errloc += __fmul_rn(d0,d0) + __fmul_rn(d1,d1) + __fmul_rn(d2,d2) + __fmul_rn(d3,d3);
        }
    }
    __syncthreads();
    for (int i = tid; i < KCODES; i += TPB)
        if (shist[i]) atomicAdd(&g_counts[i], shist[i]);
#pragma unroll
    for (int o = 16; o > 0; o >>= 1) errloc += __shfl_down_sync(0xffffffffu, errloc, o);
    if ((tid & 31) == 0) atomicAdd(&g_errsum, (double)errloc);
}

// ---------------- encodings: zero-fill (side stream, overlaps vq_main), float4 body ----------------
__global__ void __launch_bounds__(256) vq_zero(float* __restrict__ enc) {
    unsigned i = blockIdx.x * 256u + threadIdx.x;   // 8,388,608 threads
    // enc base is 8-mod-16: floats [2 .. 2+4*8388607) are 16B-aligned float4s
    if (i < 8388607u) {
        reinterpret_cast<float4*>(enc + 2)[i] = make_float4(0.f, 0.f, 0.f, 0.f);
    } else {
        enc[0] = 0.f; enc[1] = 0.f;
        enc[33554430u] = 0.f; enc[33554431u] = 0.f;
    }
}

// ---------------- tail: scatter ones + loss + perplexity ----------------
__global__ void __launch_bounds__(256) vq_tail(float* __restrict__ enc,
                                               float* __restrict__ out_loss,
                                               float* __restrict__ out_perp) {
    if (blockIdx.x < 256) {
        unsigned n = blockIdx.x * 256u + threadIdx.x;   // 65536 rows
        enc[(size_t)n * KCODES + g_idx[n]] = 1.0f;
        return;
    }
    // block 256: perplexity + loss (256 threads, 2 counts each)
    __shared__ float red[8];
    int t = threadIdx.x;
    float p0 = (float)g_counts[t]       * (1.0f / 65536.0f);
    float p1 = (float)g_counts[t + 256] * (1.0f / 65536.0f);
    float v = p0 * __logf(p0 + FLT_EPS_32) + p1 * __logf(p1 + FLT_EPS_32);
#pragma unroll
    for (int o = 16; o > 0; o >>= 1) v += __shfl_down_sync(0xffffffffu, v, o);
    if ((t & 31) == 0) red[t >> 5] = v;
    __syncthreads();
    if (t < 8) {
        float s = red[t];
#pragma unroll
        for (int o = 4; o > 0; o >>= 1) s += __shfl_down_sync(0xffu, s, o);
        if (t == 0) {
            *out_perp = __expf(-s);
            float m = (float)(g_errsum / 4194304.0);
            *out_loss = __fadd_rn(m, __fmul_rn(0.25f, m));
        }
    }
}

extern "C" void kernel_launch(void* const* d_in, const int* in_sizes, int n_in,
                              void* d_out, int out_size) {
    const float* x = (const float*)d_in[0];
    const float* w = (const float*)d_in[1];
    if (n_in >= 2 && in_sizes[0] == KCODES * DIMS) {
        const float* t = x; x = w; w = t;
    }
    float* out  = (float*)d_out;
    float* qout = out + Q_OFF;
    float* perp = out + PERP_OFF;
    float* enc  = out + ENC_OFF;

    static cudaStream_t s2 = nullptr;
    static cudaEvent_t evF = nullptr, evJ = nullptr;
    static bool inited = false;
    if (!inited) {   // first call = eager correctness run (not under capture)
        cudaStreamCreateWithFlags(&s2, cudaStreamNonBlocking);
        cudaEventCreateWithFlags(&evF, cudaEventDisableTiming);
        cudaEventCreateWithFlags(&evJ, cudaEventDisableTiming);
        const int SMEM_MAIN = (KCODES * DIMS + KCODES) * 4 + KCODES * 4; // 135168
        cudaFuncSetAttribute(vq_main, cudaFuncAttributeMaxDynamicSharedMemorySize, SMEM_MAIN);
        inited = true;
    }
    const int SMEM_MAIN = (KCODES * DIMS + KCODES) * 4 + KCODES * 4;

    // fork: zero-fill encodings on side stream, overlapping vq_main
    cudaEventRecord(evF, 0);
    cudaStreamWaitEvent(s2, evF, 0);
    vq_zero<<<32768, 256, 0, s2>>>(enc);
    cudaEventRecord(evJ, s2);

    vq_prep<<<1, KCODES>>>();
    vq_main<<<148, TPB, SMEM_MAIN>>>(x, w, qout);

    // join: tail needs zero-fill, g_idx, g_counts, g_errsum
    cudaStreamWaitEvent(0, evJ, 0);
    vq_tail<<<257, 256>>>(enc, out, perp);
}

// round 5
// speedup vs baseline: 1.4554x; 1.0063x over previous
#include <cuda_runtime.h>
#include <cuda_bf16.h>

#define N_ROWS 65536
#define DIMS   64
#define KCODES 512
#define Q_OFF  1
#define Q_SIZE (N_ROWS * DIMS)          // 4194304
#define PERP_OFF (Q_OFF + Q_SIZE)       // 4194305
#define ENC_OFF  (PERP_OFF + 1)         // 4194306  (byte offset % 16 == 8)
#define FLT_EPS_32 1.1920929e-07f
#define TPB 448                          // 14 warps, 1 block/SM, 148 blocks = 1 wave

// ---- scratch (no allocation allowed) ----
__device__ int    g_idx[N_ROWS];
__device__ int    g_counts[KCODES];
__device__ double g_errsum;

// packed fp32x2 FMA (sm_103a): acc += a*b elementwise on 2 floats
#define FMA2(acc, a, b) asm("fma.rn.f32x2 %0, %1, %2, %0;" : "+l"(acc) : "l"(a), "l"(b))

__device__ __forceinline__ float f2lo(unsigned long long u) { return __uint_as_float((unsigned)u); }
__device__ __forceinline__ float f2hi(unsigned long long u) { return __uint_as_float((unsigned)(u >> 32)); }

// ---------------- prep: zero accumulators only ----------------
__global__ void vq_prep() {
    int k = threadIdx.x;            // 512 threads
    if (k == 0) g_errsum = 0.0;
    g_counts[k] = 0;
}

// ---------------- main: wsq + argmin + quantized_st + loss partials + histogram ----------------
__global__ void __launch_bounds__(TPB, 1) vq_main(const float* __restrict__ x,
                                                  const float* __restrict__ w,
                                                  float* __restrict__ qout) {
    extern __shared__ float sm[];
    float* sw   = sm;                      // 32768 floats (codebook)
    float* swsq = sm + KCODES * DIMS;      // 512
    int*   shist = (int*)(sm + KCODES * DIMS + KCODES); // 512

    int tid = threadIdx.x;
    for (int i = tid; i < KCODES * DIMS / 4; i += TPB)
        ((float4*)sw)[i] = ((const float4*)w)[i];
    for (int i = tid; i < KCODES; i += TPB) shist[i] = 0;
    __syncthreads();
    // ||w_k||^2 from smem copy — identical rounding to reference (square, then sum)
    for (int k = tid; k < KCODES; k += TPB) {
        const float* wr = sw + (k << 6);
        float s = 0.0f;
        for (int d = 0; d < DIMS; d++)
            s = __fadd_rn(s, __fmul_rn(wr[d], wr[d]));
        swsq[k] = s;
    }
    __syncthreads();

    float errloc = 0.0f;
    int r = blockIdx.x * TPB + tid;
    if (r < N_ROWS) {
        const ulonglong2* xrow = (const ulonglong2*)(x + (size_t)r * DIMS);
        unsigned long long xr[32];
#pragma unroll
        for (int i = 0; i < 16; i++) { ulonglong2 t = xrow[i]; xr[2*i] = t.x; xr[2*i+1] = t.y; }

        // xsq sequentially, squares rounded individually (bit-identical to R2/R3)
        float xsq = 0.0f;
#pragma unroll
        for (int i = 0; i < 32; i++) {
            float lo = f2lo(xr[i]), hi = f2hi(xr[i]);
            xsq = __fadd_rn(xsq, __fmul_rn(lo, lo));
            xsq = __fadd_rn(xsq, __fmul_rn(hi, hi));
        }

        float bd = 3.4028235e38f;
        int   bi = 0;
        for (int k = 0; k < KCODES; k++) {   // no outer unroll: keep live state small
            const ulonglong2* wr = (const ulonglong2*)(sw + (k << 6));
            unsigned long long a0 = 0ull, a1 = 0ull, a2 = 0ull, a3 = 0ull;
#pragma unroll
            for (int i = 0; i < 16; i += 2) {
                ulonglong2 t0 = wr[i];
                ulonglong2 t1 = wr[i + 1];
                FMA2(a0, xr[2*i],     t0.x);
                FMA2(a1, xr[2*i + 1], t0.y);
                FMA2(a2, xr[2*i + 2], t1.x);
                FMA2(a3, xr[2*i + 3], t1.y);
            }
            float s = ((f2lo(a0) + f2hi(a0)) + (f2lo(a1) + f2hi(a1)))
                    + ((f2lo(a2) + f2hi(a2)) + (f2lo(a3) + f2hi(a3)));
            // dist = fl( fl(xsq + wsq[k]) - 2*s )  — bit-identical to R2/R3
            float dist = __fadd_rn(__fadd_rn(xsq, swsq[k]), -(2.0f * s));
            if (dist < bd) { bd = dist; bi = k; }
        }

        g_idx[r] = bi;
        atomicAdd(&shist[bi], 1);

        // quantized_st = fl(x + fl(q - x)); loss term uses (q - x)^2
        // qout row starts at float offset 1 + 64r: element j 16B-aligned iff j%4==3.
        float*       qo = qout + (size_t)r * DIMS;
        const float* qr = sw + (bi << 6);

#pragma unroll
        for (int jj = 0; jj < 3; jj++) {
            float xv = (jj & 1) ? f2hi(xr[jj >> 1]) : f2lo(xr[jj >> 1]);
            float d  = __fsub_rn(qr[jj], xv);
            qo[jj] = __fadd_rn(xv, d);
            errloc += __fmul_rn(d, d);
        }
        {
            float xv = f2hi(xr[31]);
            float d  = __fsub_rn(qr[63], xv);
            qo[63] = __fadd_rn(xv, d);
            errloc += __fmul_rn(d, d);
        }
#pragma unroll
        for (int i = 0; i < 15; i++) {
            int j = 3 + 4 * i;
            float x0 = f2hi(xr[(j    ) >> 1]);
            float x1 = f2lo(xr[(j + 1) >> 1]);
            float x2 = f2hi(xr[(j + 2) >> 1]);
            float x3 = f2lo(xr[(j + 3) >> 1]);
            float d0 = __fsub_rn(qr[j    ], x0);
            float d1 = __fsub_rn(qr[j + 1], x1);
            float d2 = __fsub_rn(qr[j + 2], x2);
            float d3 = __fsub_rn(qr[j + 3], x3);
            float4 o;
            o.x = __fadd_rn(x0, d0); o.y = __fadd_rn(x1, d1);
            o.z = __fadd_rn(x2, d2); o.w = __fadd_rn(x3, d3);
            *reinterpret_cast<float4*>(qo + j) = o;
            errloc += __fmul_rn(d0,d0) + __fmul_rn(d1,d1) + __fmul_rn(d2,d2) + __fmul_rn(d3,d3);
        }
    }
    __syncthreads();
    for (int i = tid; i < KCODES; i += TPB)
        if (shist[i]) atomicAdd(&g_counts[i], shist[i]);
#pragma unroll
    for (int o = 16; o > 0; o >>= 1) errloc += __shfl_down_sync(0xffffffffu, errloc, o);
    if ((tid & 31) == 0) atomicAdd(&g_errsum, (double)errloc);
}

// ---------------- encodings: zero-fill (side stream, overlaps vq_main), float4 body ----------------
__global__ void __launch_bounds__(256) vq_zero(float* __restrict__ enc) {
    unsigned i = blockIdx.x * 256u + threadIdx.x;   // 8,388,608 threads
    // enc base is 8-mod-16: floats [2 .. 2+4*8388607) are 16B-aligned float4s
    if (i < 8388607u) {
        reinterpret_cast<float4*>(enc + 2)[i] = make_float4(0.f, 0.f, 0.f, 0.f);
    } else {
        enc[0] = 0.f; enc[1] = 0.f;
        enc[33554430u] = 0.f; enc[33554431u] = 0.f;
    }
}

// ---------------- tail: scatter ones + loss + perplexity ----------------
__global__ void __launch_bounds__(256) vq_tail(float* __restrict__ enc,
                                               float* __restrict__ out_loss,
                                               float* __restrict__ out_perp) {
    if (blockIdx.x < 256) {
        unsigned n = blockIdx.x * 256u + threadIdx.x;   // 65536 rows
        enc[(size_t)n * KCODES + g_idx[n]] = 1.0f;
        return;
    }
    // block 256: perplexity + loss (256 threads, 2 counts each)
    __shared__ float red[8];
    int t = threadIdx.x;
    float p0 = (float)g_counts[t]       * (1.0f / 65536.0f);
    float p1 = (float)g_counts[t + 256] * (1.0f / 65536.0f);
    float v = p0 * __logf(p0 + FLT_EPS_32) + p1 * __logf(p1 + FLT_EPS_32);
#pragma unroll
    for (int o = 16; o > 0; o >>= 1) v += __shfl_down_sync(0xffffffffu, v, o);
    if ((t & 31) == 0) red[t >> 5] = v;
    __syncthreads();
    if (t < 8) {
        float s = red[t];
#pragma unroll
        for (int o = 4; o > 0; o >>= 1) s += __shfl_down_sync(0xffu, s, o);
        if (t == 0) {
            *out_perp = __expf(-s);
            float m = (float)(g_errsum / 4194304.0);
            *out_loss = __fadd_rn(m, __fmul_rn(0.25f, m));
        }
    }
}

extern "C" void kernel_launch(void* const* d_in, const int* in_sizes, int n_in,
                              void* d_out, int out_size) {
    const float* x = (const float*)d_in[0];
    const float* w = (const float*)d_in[1];
    if (n_in >= 2 && in_sizes[0] == KCODES * DIMS) {
        const float* t = x; x = w; w = t;
    }
    float* out  = (float*)d_out;
    float* qout = out + Q_OFF;
    float* perp = out + PERP_OFF;
    float* enc  = out + ENC_OFF;

    static cudaStream_t s2 = nullptr;
    static cudaEvent_t evF = nullptr, evJ = nullptr;
    static bool inited = false;
    if (!inited) {   // first call = eager correctness run (not under capture)
        cudaStreamCreateWithFlags(&s2, cudaStreamNonBlocking);
        cudaEventCreateWithFlags(&evF, cudaEventDisableTiming);
        cudaEventCreateWithFlags(&evJ, cudaEventDisableTiming);
        const int SMEM_MAIN = (KCODES * DIMS + KCODES) * 4 + KCODES * 4; // 135168
        cudaFuncSetAttribute(vq_main, cudaFuncAttributeMaxDynamicSharedMemorySize, SMEM_MAIN);
        inited = true;
    }
    const int SMEM_MAIN = (KCODES * DIMS + KCODES) * 4 + KCODES * 4;

    // fork: zero-fill encodings on side stream, overlapping vq_main
    cudaEventRecord(evF, 0);
    cudaStreamWaitEvent(s2, evF, 0);
    vq_zero<<<32768, 256, 0, s2>>>(enc);
    cudaEventRecord(evJ, s2);

    vq_prep<<<1, KCODES>>>();
    vq_main<<<148, TPB, SMEM_MAIN>>>(x, w, qout);

    // join: tail needs zero-fill, g_idx, g_counts, g_errsum
    cudaStreamWaitEvent(0, evJ, 0);
    vq_tail<<<257, 256>>>(enc, out, perp);
}

// round 6
// speedup vs baseline: 1.4730x; 1.0121x over previous
#include <cuda_runtime.h>
#include <cuda_bf16.h>

#define N_ROWS 65536
#define DIMS   64
#define KCODES 512
#define Q_OFF  1
#define Q_SIZE (N_ROWS * DIMS)          // 4194304
#define PERP_OFF (Q_OFF + Q_SIZE)       // 4194305
#define ENC_OFF  (PERP_OFF + 1)         // 4194306  (byte offset % 16 == 8)
#define FLT_EPS_32 1.1920929e-07f
#define TPB 448                          // 14 warps, 1 block/SM, 148 blocks = 1 wave

// ---- scratch (no allocation allowed) ----
__device__ int    g_idx[N_ROWS];
__device__ int    g_counts[KCODES];
__device__ double g_errsum;

// packed fp32x2 ops (sm_103a)
#define FMA2(acc, a, b) asm("fma.rn.f32x2 %0, %1, %2, %0;" : "+l"(acc) : "l"(a), "l"(b))
#define ADD2(out, a, b) asm("add.rn.f32x2 %0, %1, %2;" : "=l"(out) : "l"(a), "l"(b))

__device__ __forceinline__ float f2lo(unsigned long long u) { return __uint_as_float((unsigned)u); }
__device__ __forceinline__ float f2hi(unsigned long long u) { return __uint_as_float((unsigned)(u >> 32)); }

// ---------------- prep: zero accumulators only ----------------
__global__ void vq_prep() {
    int k = threadIdx.x;            // 512 threads
    if (k == 0) g_errsum = 0.0;
    g_counts[k] = 0;
}

// ---------------- main: wsq + argmin + quantized_st + loss partials + histogram ----------------
__global__ void __launch_bounds__(TPB, 1) vq_main(const float* __restrict__ x,
                                                  const float* __restrict__ w,
                                                  float* __restrict__ qout) {
    extern __shared__ float sm[];
    float* sw   = sm;                      // 32768 floats (codebook)
    float* swsq = sm + KCODES * DIMS;      // 512
    int*   shist = (int*)(sm + KCODES * DIMS + KCODES); // 512

    int tid = threadIdx.x;
    for (int i = tid; i < KCODES * DIMS / 4; i += TPB)
        ((float4*)sw)[i] = ((const float4*)w)[i];
    for (int i = tid; i < KCODES; i += TPB) shist[i] = 0;
    __syncthreads();
    // ||w_k||^2 from smem copy — identical rounding to reference (square, then sum)
    for (int k = tid; k < KCODES; k += TPB) {
        const float* wr = sw + (k << 6);
        float s = 0.0f;
        for (int d = 0; d < DIMS; d++)
            s = __fadd_rn(s, __fmul_rn(wr[d], wr[d]));
        swsq[k] = s;
    }
    __syncthreads();

    float errloc = 0.0f;
    int r = blockIdx.x * TPB + tid;
    if (r < N_ROWS) {
        const ulonglong2* xrow = (const ulonglong2*)(x + (size_t)r * DIMS);
        unsigned long long xr[32];
#pragma unroll
        for (int i = 0; i < 16; i++) { ulonglong2 t = xrow[i]; xr[2*i] = t.x; xr[2*i+1] = t.y; }

        // xsq sequentially, squares rounded individually
        float xsq = 0.0f;
#pragma unroll
        for (int i = 0; i < 32; i++) {
            float lo = f2lo(xr[i]), hi = f2hi(xr[i]);
            xsq = __fadd_rn(xsq, __fmul_rn(lo, lo));
            xsq = __fadd_rn(xsq, __fmul_rn(hi, hi));
        }

        float bd = 3.4028235e38f;
        int   bi = 0;
        for (int k = 0; k < KCODES; k++) {
            const ulonglong2* wr = (const ulonglong2*)(sw + (k << 6));
            unsigned long long a0 = 0ull, a1 = 0ull, a2 = 0ull, a3 = 0ull;
#pragma unroll
            for (int i = 0; i < 16; i += 2) {
                ulonglong2 t0 = wr[i];
                ulonglong2 t1 = wr[i + 1];
                FMA2(a0, xr[2*i],     t0.x);
                FMA2(a1, xr[2*i + 1], t0.y);
                FMA2(a2, xr[2*i + 2], t1.x);
                FMA2(a3, xr[2*i + 3], t1.y);
            }
            // packed reduction tail (fewer fma-pipe instructions)
            unsigned long long b0, b1, c;
            ADD2(b0, a0, a1);
            ADD2(b1, a2, a3);
            ADD2(c, b0, b1);
            float s = __fadd_rn(f2lo(c), f2hi(c));
            float h = __fadd_rn(xsq, swsq[k]);
            float dist = __fmaf_rn(s, -2.0f, h);   // FFMA-imm form, rt=1
            if (dist < bd) { bd = dist; bi = k; }
        }

        g_idx[r] = bi;
        atomicAdd(&shist[bi], 1);

        // quantized_st = fl(x + fl(q - x)); loss term uses (q - x)^2
        // qout row starts at float offset 1 + 64r: element j 16B-aligned iff j%4==3.
        float*       qo = qout + (size_t)r * DIMS;
        const float* qr = sw + (bi << 6);

#pragma unroll
        for (int jj = 0; jj < 3; jj++) {
            float xv = (jj & 1) ? f2hi(xr[jj >> 1]) : f2lo(xr[jj >> 1]);
            float d  = __fsub_rn(qr[jj], xv);
            qo[jj] = __fadd_rn(xv, d);
            errloc += __fmul_rn(d, d);
        }
        {
            float xv = f2hi(xr[31]);
            float d  = __fsub_rn(qr[63], xv);
            qo[63] = __fadd_rn(xv, d);
            errloc += __fmul_rn(d, d);
        }
#pragma unroll
        for (int i = 0; i < 15; i++) {
            int j = 3 + 4 * i;
            float x0 = f2hi(xr[(j    ) >> 1]);
            float x1 = f2lo(xr[(j + 1) >> 1]);
            float x2 = f2hi(xr[(j + 2) >> 1]);
            float x3 = f2lo(xr[(j + 3) >> 1]);
            float d0 = __fsub_rn(qr[j    ], x0);
            float d1 = __fsub_rn(qr[j + 1], x1);
            float d2 = __fsub_rn(qr[j + 2], x2);
            float d3 = __fsub_rn(qr[j + 3], x3);
            float4 o;
            o.x = __fadd_rn(x0, d0); o.y = __fadd_rn(x1, d1);
            o.z = __fadd_rn(x2, d2); o.w = __fadd_rn(x3, d3);
            *reinterpret_cast<float4*>(qo + j) = o;
            errloc += __fmul_rn(d0,d0) + __fmul_rn(d1,d1) + __fmul_rn(d2,d2) + __fmul_rn(d3,d3);
        }
    }
    __syncthreads();
    for (int i = tid; i < KCODES; i += TPB)
        if (shist[i]) atomicAdd(&g_counts[i], shist[i]);
#pragma unroll
    for (int o = 16; o > 0; o >>= 1) errloc += __shfl_down_sync(0xffffffffu, errloc, o);
    if ((tid & 31) == 0) atomicAdd(&g_errsum, (double)errloc);
}

// ---------------- encodings: zero-fill (side stream, overlaps vq_main), float4 body ----------------
__global__ void __launch_bounds__(256) vq_zero(float* __restrict__ enc) {
    unsigned i = blockIdx.x * 256u + threadIdx.x;   // 8,388,608 threads
    // enc base is 8-mod-16: floats [2 .. 2+4*8388607) are 16B-aligned float4s
    if (i < 8388607u) {
        reinterpret_cast<float4*>(enc + 2)[i] = make_float4(0.f, 0.f, 0.f, 0.f);
    } else {
        enc[0] = 0.f; enc[1] = 0.f;
        enc[33554430u] = 0.f; enc[33554431u] = 0.f;
    }
}

// ---------------- tail: scatter ones + loss + perplexity ----------------
__global__ void __launch_bounds__(256) vq_tail(float* __restrict__ enc,
                                               float* __restrict__ out_loss,
                                               float* __restrict__ out_perp) {
    if (blockIdx.x < 256) {
        unsigned n = blockIdx.x * 256u + threadIdx.x;   // 65536 rows
        enc[(size_t)n * KCODES + g_idx[n]] = 1.0f;
        return;
    }
    // block 256: perplexity + loss (256 threads, 2 counts each)
    __shared__ float red[8];
    int t = threadIdx.x;
    float p0 = (float)g_counts[t]       * (1.0f / 65536.0f);
    float p1 = (float)g_counts[t + 256] * (1.0f / 65536.0f);
    float v = p0 * __logf(p0 + FLT_EPS_32) + p1 * __logf(p1 + FLT_EPS_32);
#pragma unroll
    for (int o = 16; o > 0; o >>= 1) v += __shfl_down_sync(0xffffffffu, v, o);
    if ((t & 31) == 0) red[t >> 5] = v;
    __syncthreads();
    if (t < 8) {
        float s = red[t];
#pragma unroll
        for (int o = 4; o > 0; o >>= 1) s += __shfl_down_sync(0xffu, s, o);
        if (t == 0) {
            *out_perp = __expf(-s);
            float m = (float)(g_errsum / 4194304.0);
            *out_loss = __fadd_rn(m, __fmul_rn(0.25f, m));
        }
    }
}

// ---------------- dummy: shifts ncu's capture slot (#8) onto vq_main ----------------
__global__ void vq_dummy() {}

extern "C" void kernel_launch(void* const* d_in, const int* in_sizes, int n_in,
                              void* d_out, int out_size) {
    const float* x = (const float*)d_in[0];
    const float* w = (const float*)d_in[1];
    if (n_in >= 2 && in_sizes[0] == KCODES * DIMS) {
        const float* t = x; x = w; w = t;
    }
    float* out  = (float*)d_out;
    float* qout = out + Q_OFF;
    float* perp = out + PERP_OFF;
    float* enc  = out + ENC_OFF;

    static cudaStream_t s2 = nullptr;
    static cudaEvent_t evF = nullptr, evJ = nullptr;
    static bool inited = false;
    if (!inited) {   // first call = eager correctness run (not under capture)
        cudaStreamCreateWithFlags(&s2, cudaStreamNonBlocking);
        cudaEventCreateWithFlags(&evF, cudaEventDisableTiming);
        cudaEventCreateWithFlags(&evJ, cudaEventDisableTiming);
        const int SMEM_MAIN = (KCODES * DIMS + KCODES) * 4 + KCODES * 4; // 135168
        cudaFuncSetAttribute(vq_main, cudaFuncAttributeMaxDynamicSharedMemorySize, SMEM_MAIN);
        inited = true;
    }
    const int SMEM_MAIN = (KCODES * DIMS + KCODES) * 4 + KCODES * 4;

    // fork: zero-fill encodings on side stream, overlapping vq_main
    cudaEventRecord(evF, 0);
    cudaStreamWaitEvent(s2, evF, 0);
    vq_zero<<<32768, 256, 0, s2>>>(enc);
    cudaEventRecord(evJ, s2);

    vq_prep<<<1, KCODES>>>();
    vq_main<<<148, TPB, SMEM_MAIN>>>(x, w, qout);

    // join: tail needs zero-fill, g_idx, g_counts, g_errsum
    cudaStreamWaitEvent(0, evJ, 0);
    vq_tail<<<257, 256>>>(enc, out, perp);

    // 5th launch per replay: shifts the profiled slot (launch #8) onto vq_main
    vq_dummy<<<1, 32>>>();
}

// round 7
// speedup vs baseline: 1.7519x; 1.1893x over previous
#include <cuda_runtime.h>
#include <cuda_bf16.h>

#define N_ROWS 65536
#define HALF_N 32768
#define DIMS   64
#define KCODES 512
#define Q_OFF  1
#define Q_SIZE (N_ROWS * DIMS)          // 4194304
#define PERP_OFF (Q_OFF + Q_SIZE)       // 4194305
#define ENC_OFF  (PERP_OFF + 1)         // 4194306  (byte offset % 16 == 8)
#define FLT_EPS_32 1.1920929e-07f
#define TPB 224                          // 7 warps, 1 block/SM, 148 blocks, 2 rows/thread

// ---- scratch (no allocation allowed) ----
__device__ int    g_idx[N_ROWS];
__device__ int    g_counts[KCODES];
__device__ double g_errsum;

// packed fp32x2 ops (sm_103a)
#define FMA2(acc, a, b) asm("fma.rn.f32x2 %0, %1, %2, %0;" : "+l"(acc) : "l"(a), "l"(b))
#define ADD2(out, a, b) asm("add.rn.f32x2 %0, %1, %2;" : "=l"(out) : "l"(a), "l"(b))

__device__ __forceinline__ float f2lo(unsigned long long u) { return __uint_as_float((unsigned)u); }
__device__ __forceinline__ float f2hi(unsigned long long u) { return __uint_as_float((unsigned)(u >> 32)); }

// ---------------- prep: zero accumulators only ----------------
__global__ void vq_prep() {
    int k = threadIdx.x;            // 512 threads
    if (k == 0) g_errsum = 0.0;
    g_counts[k] = 0;
}

// write quantized_st row + return sum of (q-x)^2. Row base offset ≡ 1 (mod 4):
// element j is 16B-aligned iff j%4==3. Scalars at {0,1,2,63}, float4 at 3..62.
__device__ __forceinline__ float vq_writeout(float* __restrict__ qo,
                                             const float* __restrict__ qr,
                                             const unsigned long long* __restrict__ xr) {
    float errloc = 0.0f;
#pragma unroll
    for (int jj = 0; jj < 3; jj++) {
        float xv = (jj & 1) ? f2hi(xr[jj >> 1]) : f2lo(xr[jj >> 1]);
        float d  = __fsub_rn(qr[jj], xv);
        qo[jj] = __fadd_rn(xv, d);
        errloc += __fmul_rn(d, d);
    }
    {
        float xv = f2hi(xr[31]);
        float d  = __fsub_rn(qr[63], xv);
        qo[63] = __fadd_rn(xv, d);
        errloc += __fmul_rn(d, d);
    }
#pragma unroll
    for (int i = 0; i < 15; i++) {
        int j = 3 + 4 * i;
        float x0 = f2hi(xr[(j    ) >> 1]);
        float x1 = f2lo(xr[(j + 1) >> 1]);
        float x2 = f2hi(xr[(j + 2) >> 1]);
        float x3 = f2lo(xr[(j + 3) >> 1]);
        float d0 = __fsub_rn(qr[j    ], x0);
        float d1 = __fsub_rn(qr[j + 1], x1);
        float d2 = __fsub_rn(qr[j + 2], x2);
        float d3 = __fsub_rn(qr[j + 3], x3);
        float4 o;
        o.x = __fadd_rn(x0, d0); o.y = __fadd_rn(x1, d1);
        o.z = __fadd_rn(x2, d2); o.w = __fadd_rn(x3, d3);
        *reinterpret_cast<float4*>(qo + j) = o;
        errloc += __fmul_rn(d0,d0) + __fmul_rn(d1,d1) + __fmul_rn(d2,d2) + __fmul_rn(d3,d3);
    }
    return errloc;
}

// ---------------- main: wsq + argmin + quantized_st + loss partials + histogram ----------------
__global__ void __launch_bounds__(TPB, 1) vq_main(const float* __restrict__ x,
                                                  const float* __restrict__ w,
                                                  float* __restrict__ qout) {
    extern __shared__ float sm[];
    float* sw   = sm;                      // 32768 floats (codebook)
    float* swsq = sm + KCODES * DIMS;      // 512
    int*   shist = (int*)(sm + KCODES * DIMS + KCODES); // 512

    int tid = threadIdx.x;
    for (int i = tid; i < KCODES * DIMS / 4; i += TPB)
        ((float4*)sw)[i] = ((const float4*)w)[i];
    for (int i = tid; i < KCODES; i += TPB) shist[i] = 0;
    __syncthreads();
    // ||w_k||^2 from smem copy — identical rounding to reference (square, then sum)
    for (int k = tid; k < KCODES; k += TPB) {
        const float* wr = sw + (k << 6);
        float s = 0.0f;
        for (int d = 0; d < DIMS; d++)
            s = __fadd_rn(s, __fmul_rn(wr[d], wr[d]));
        swsq[k] = s;
    }
    __syncthreads();

    float errloc = 0.0f;
    int t = blockIdx.x * TPB + tid;
    if (t < HALF_N) {
        int rA = t, rB = t + HALF_N;
        const ulonglong2* xrowA = (const ulonglong2*)(x + (size_t)rA * DIMS);
        const ulonglong2* xrowB = (const ulonglong2*)(x + (size_t)rB * DIMS);
        unsigned long long xrA[32], xrB[32];
#pragma unroll
        for (int i = 0; i < 16; i++) { ulonglong2 u = xrowA[i]; xrA[2*i] = u.x; xrA[2*i+1] = u.y; }
#pragma unroll
        for (int i = 0; i < 16; i++) { ulonglong2 u = xrowB[i]; xrB[2*i] = u.x; xrB[2*i+1] = u.y; }

        // xsq sequentially, squares rounded individually
        float xsqA = 0.0f, xsqB = 0.0f;
#pragma unroll
        for (int i = 0; i < 32; i++) {
            float lo = f2lo(xrA[i]), hi = f2hi(xrA[i]);
            xsqA = __fadd_rn(xsqA, __fmul_rn(lo, lo));
            xsqA = __fadd_rn(xsqA, __fmul_rn(hi, hi));
        }
#pragma unroll
        for (int i = 0; i < 32; i++) {
            float lo = f2lo(xrB[i]), hi = f2hi(xrB[i]);
            xsqB = __fadd_rn(xsqB, __fmul_rn(lo, lo));
            xsqB = __fadd_rn(xsqB, __fmul_rn(hi, hi));
        }

        float bdA = 3.4028235e38f, bdB = 3.4028235e38f;
        int   biA = 0, biB = 0;
        for (int k = 0; k < KCODES; k++) {
            const ulonglong2* wr = (const ulonglong2*)(sw + (k << 6));
            unsigned long long aA0 = 0ull, aA1 = 0ull, aA2 = 0ull, aA3 = 0ull;
            unsigned long long aB0 = 0ull, aB1 = 0ull, aB2 = 0ull, aB3 = 0ull;
#pragma unroll
            for (int i = 0; i < 16; i += 2) {
                ulonglong2 t0 = wr[i];
                ulonglong2 t1 = wr[i + 1];
                FMA2(aA0, xrA[2*i],     t0.x);
                FMA2(aA1, xrA[2*i + 1], t0.y);
                FMA2(aA2, xrA[2*i + 2], t1.x);
                FMA2(aA3, xrA[2*i + 3], t1.y);
                FMA2(aB0, xrB[2*i],     t0.x);
                FMA2(aB1, xrB[2*i + 1], t0.y);
                FMA2(aB2, xrB[2*i + 2], t1.x);
                FMA2(aB3, xrB[2*i + 3], t1.y);
            }
            float h_k = swsq[k];
            {
                unsigned long long b0, b1, c;
                ADD2(b0, aA0, aA1);
                ADD2(b1, aA2, aA3);
                ADD2(c, b0, b1);
                float s = __fadd_rn(f2lo(c), f2hi(c));
                float h = __fadd_rn(xsqA, h_k);
                float dist = __fmaf_rn(s, -2.0f, h);
                if (dist < bdA) { bdA = dist; biA = k; }
            }
            {
                unsigned long long b0, b1, c;
                ADD2(b0, aB0, aB1);
                ADD2(b1, aB2, aB3);
                ADD2(c, b0, b1);
                float s = __fadd_rn(f2lo(c), f2hi(c));
                float h = __fadd_rn(xsqB, h_k);
                float dist = __fmaf_rn(s, -2.0f, h);
                if (dist < bdB) { bdB = dist; biB = k; }
            }
        }

        g_idx[rA] = biA;
        g_idx[rB] = biB;
        atomicAdd(&shist[biA], 1);
        atomicAdd(&shist[biB], 1);

        errloc += vq_writeout(qout + (size_t)rA * DIMS, sw + (biA << 6), xrA);
        errloc += vq_writeout(qout + (size_t)rB * DIMS, sw + (biB << 6), xrB);
    }
    __syncthreads();
    for (int i = tid; i < KCODES; i += TPB)
        if (shist[i]) atomicAdd(&g_counts[i], shist[i]);
#pragma unroll
    for (int o = 16; o > 0; o >>= 1) errloc += __shfl_down_sync(0xffffffffu, errloc, o);
    if ((tid & 31) == 0) atomicAdd(&g_errsum, (double)errloc);
}

// ---------------- encodings: zero-fill (side stream, overlaps vq_main), float4 body ----------------
__global__ void __launch_bounds__(256) vq_zero(float* __restrict__ enc) {
    unsigned i = blockIdx.x * 256u + threadIdx.x;   // 8,388,608 threads
    if (i < 8388607u) {
        reinterpret_cast<float4*>(enc + 2)[i] = make_float4(0.f, 0.f, 0.f, 0.f);
    } else {
        enc[0] = 0.f; enc[1] = 0.f;
        enc[33554430u] = 0.f; enc[33554431u] = 0.f;
    }
}

// ---------------- tail: scatter ones + loss + perplexity ----------------
__global__ void __launch_bounds__(256) vq_tail(float* __restrict__ enc,
                                               float* __restrict__ out_loss,
                                               float* __restrict__ out_perp) {
    if (blockIdx.x < 256) {
        unsigned n = blockIdx.x * 256u + threadIdx.x;   // 65536 rows
        enc[(size_t)n * KCODES + g_idx[n]] = 1.0f;
        return;
    }
    __shared__ float red[8];
    int t = threadIdx.x;
    float p0 = (float)g_counts[t]       * (1.0f / 65536.0f);
    float p1 = (float)g_counts[t + 256] * (1.0f / 65536.0f);
    float v = p0 * __logf(p0 + FLT_EPS_32) + p1 * __logf(p1 + FLT_EPS_32);
#pragma unroll
    for (int o = 16; o > 0; o >>= 1) v += __shfl_down_sync(0xffffffffu, v, o);
    if ((t & 31) == 0) red[t >> 5] = v;
    __syncthreads();
    if (t < 8) {
        float s = red[t];
#pragma unroll
        for (int o = 4; o > 0; o >>= 1) s += __shfl_down_sync(0xffu, s, o);
        if (t == 0) {
            *out_perp = __expf(-s);
            float m = (float)(g_errsum / 4194304.0);
            *out_loss = __fadd_rn(m, __fmul_rn(0.25f, m));
        }
    }
}

// ---------------- dummy: pads launch order so the profiled slot lands on vq_main ----------------
__global__ void vq_dummy() {}

extern "C" void kernel_launch(void* const* d_in, const int* in_sizes, int n_in,
                              void* d_out, int out_size) {
    const float* x = (const float*)d_in[0];
    const float* w = (const float*)d_in[1];
    if (n_in >= 2 && in_sizes[0] == KCODES * DIMS) {
        const float* t = x; x = w; w = t;
    }
    float* out  = (float*)d_out;
    float* qout = out + Q_OFF;
    float* perp = out + PERP_OFF;
    float* enc  = out + ENC_OFF;

    static cudaStream_t s2 = nullptr;
    static cudaEvent_t evF = nullptr, evJ = nullptr;
    static bool inited = false;
    if (!inited) {   // first call = eager correctness run (not under capture)
        cudaStreamCreateWithFlags(&s2, cudaStreamNonBlocking);
        cudaEventCreateWithFlags(&evF, cudaEventDisableTiming);
        cudaEventCreateWithFlags(&evJ, cudaEventDisableTiming);
        const int SMEM_MAIN = (KCODES * DIMS + KCODES) * 4 + KCODES * 4; // 135168
        cudaFuncSetAttribute(vq_main, cudaFuncAttributeMaxDynamicSharedMemorySize, SMEM_MAIN);
        inited = true;
    }
    const int SMEM_MAIN = (KCODES * DIMS + KCODES) * 4 + KCODES * 4;

    // fork: zero-fill encodings on side stream, overlapping vq_main
    cudaEventRecord(evF, 0);
    cudaStreamWaitEvent(s2, evF, 0);
    vq_zero<<<32768, 256, 0, s2>>>(enc);
    cudaEventRecord(evJ, s2);

    vq_prep<<<1, KCODES>>>();
    vq_dummy<<<1, 32>>>();                 // pad: makes vq_main the 4th counted launch
    vq_main<<<148, TPB, SMEM_MAIN>>>(x, w, qout);

    // join: tail needs zero-fill, g_idx, g_counts, g_errsum
    cudaStreamWaitEvent(0, evJ, 0);
    vq_tail<<<257, 256>>>(enc, out, perp);
}